// round 1
// baseline (speedup 1.0000x reference)
#include <cuda_runtime.h>
#include <math.h>

#define FULL_MASK 0xffffffffu
#define MAX_B 4096
#define DLEV 5

// Per-row totals scratch (no device allocation allowed; static __device__ is the sanctioned path)
__device__ float g_row_total[MAX_B];

__global__ void hier_loss_row_kernel(
    const float* __restrict__ y_pred,
    const float* __restrict__ y_true,
    const float* __restrict__ class_weights,
    const int*   __restrict__ path_ids,   // [C, D]
    const int*   __restrict__ path_len,   // [C]
    const int*   __restrict__ sib_start,  // [C, D]
    const int*   __restrict__ sib_size,   // [C, D]
    int B, int C)
{
    const int warp = threadIdx.x >> 5;
    const int lane = threadIdx.x & 31;
    const int warps_per_block = blockDim.x >> 5;
    const int row = blockIdx.x * warps_per_block + warp;
    if (row >= B) return;

    const float* prow = y_pred + (size_t)row * C;
    const float* trow = y_true + (size_t)row * C;

    // ---- fused dual argmax over C (float4 vectorized, first-index tiebreak) ----
    float pv = -INFINITY, tv = -INFINITY;
    int   pi = 0,          ti = 0;

    const int n4 = C >> 2;  // 682 for C=2728
    const float4* p4 = reinterpret_cast<const float4*>(prow);
    const float4* t4 = reinterpret_cast<const float4*>(trow);

    for (int i = lane; i < n4; i += 32) {
        float4 a = p4[i];
        float4 b = t4[i];
        int base = i << 2;
        // strictly-greater keeps the earliest index within a lane (indices increase)
        if (a.x > pv) { pv = a.x; pi = base;     }
        if (a.y > pv) { pv = a.y; pi = base + 1; }
        if (a.z > pv) { pv = a.z; pi = base + 2; }
        if (a.w > pv) { pv = a.w; pi = base + 3; }
        if (b.x > tv) { tv = b.x; ti = base;     }
        if (b.y > tv) { tv = b.y; ti = base + 1; }
        if (b.z > tv) { tv = b.z; ti = base + 2; }
        if (b.w > tv) { tv = b.w; ti = base + 3; }
    }
    // scalar tail (none for C=2728, kept for generality)
    for (int c = (n4 << 2) + lane; c < C; c += 32) {
        float a = prow[c];
        float b = trow[c];
        if (a > pv) { pv = a; pi = c; }
        if (b > tv) { tv = b; ti = c; }
    }

    // warp reduce: max value, lowest index on ties
    #pragma unroll
    for (int off = 16; off > 0; off >>= 1) {
        float opv = __shfl_down_sync(FULL_MASK, pv, off);
        int   opi = __shfl_down_sync(FULL_MASK, pi, off);
        if (opv > pv || (opv == pv && opi < pi)) { pv = opv; pi = opi; }
        float otv = __shfl_down_sync(FULL_MASK, tv, off);
        int   oti = __shfl_down_sync(FULL_MASK, ti, off);
        if (otv > tv || (otv == tv && oti < ti)) { tv = otv; ti = oti; }
    }

    if (lane == 0) {
        const int pred_top = pi;
        const int true_top = ti;
        const int len_p = path_len[pred_top];
        const int len_t = path_len[true_top];
        const int lmin  = (len_p < len_t) ? len_p : len_t;

        float total = 0.0f;
        const int diff = (len_p > len_t) ? (len_p - len_t) : (len_t - len_p);

        if (diff != 0) {   // otherwise total is exactly 0
            float local = 0.0f;
            #pragma unroll
            for (int l = 0; l < DLEV; l++) {
                if (l < lmin) {
                    const int start = sib_start[true_top * DLEV + l];
                    const int size  = sib_size [true_top * DLEV + l];
                    const int tid_l = path_ids [true_top * DLEV + l];

                    // lse of (y_pred * 0/1 mask): masked-out classes contribute exp(0)=1
                    float s = (float)(C - size);
                    for (int c = start; c < start + size; c++) {
                        s += expf(prow[c]);
                    }
                    const float lse = logf(s);
                    const float ce  = lse - prow[tid_l];
                    const float h   = (float)(len_t - l - 1);
                    local += expf(-0.5f * h) * ce;
                }
            }
            total = local * (1.5f * (float)diff) * class_weights[true_top];
        }
        g_row_total[row] = total;
    }
}

__global__ void hier_loss_reduce_kernel(float* __restrict__ out, int B)
{
    __shared__ float s[1024];
    float sum = 0.0f;
    for (int i = threadIdx.x; i < B; i += blockDim.x) sum += g_row_total[i];
    s[threadIdx.x] = sum;
    __syncthreads();
    for (int k = blockDim.x >> 1; k > 0; k >>= 1) {
        if (threadIdx.x < k) s[threadIdx.x] += s[threadIdx.x + k];
        __syncthreads();
    }
    if (threadIdx.x == 0) out[0] = s[0] / (float)B;
}

extern "C" void kernel_launch(void* const* d_in, const int* in_sizes, int n_in,
                              void* d_out, int out_size)
{
    const float* y_pred        = (const float*)d_in[0];
    const float* y_true        = (const float*)d_in[1];
    const float* class_weights = (const float*)d_in[2];
    const int*   path_ids      = (const int*)  d_in[3];
    const int*   path_len      = (const int*)  d_in[4];
    const int*   sib_start     = (const int*)  d_in[5];
    const int*   sib_size      = (const int*)  d_in[6];

    const int C = in_sizes[2];            // 2728
    const int B = in_sizes[0] / C;        // 4096

    const int threads = 256;              // 8 warps = 8 rows per block
    const int rows_per_block = threads / 32;
    const int blocks = (B + rows_per_block - 1) / rows_per_block;

    hier_loss_row_kernel<<<blocks, threads>>>(
        y_pred, y_true, class_weights, path_ids, path_len, sib_start, sib_size, B, C);
    hier_loss_reduce_kernel<<<1, 1024>>>((float*)d_out, B);
}